// round 4
// baseline (speedup 1.0000x reference)
#include <cuda_runtime.h>

#define NXD 256
#define NTOT (NXD*NXD*NXD)

// SMEM layout (floats):
//  F  : 64 rows  x 128  (feats, k-major, rows 0..62 used)
//  H  : 128 rows x 128  (activations, o-major rows, p contiguous)
//  Ws : 192 rows x 128  (current layer weights, k-major)
//  RET: 128 float4      (trilinear results)
#define F_OFF   0
#define H_OFF   (64*128)
#define W_OFF   (H_OFF + 128*128)
#define RET_OFF (W_OFF + 192*128)
#define SMEM_FLOATS (RET_OFF + 128*4)
#define SMEM_BYTES  (SMEM_FLOATS * 4)

typedef unsigned long long u64;

__device__ float4 g_data[NTOT];   // 256 MB static scratch (grid value + gradient)

static __device__ __forceinline__ u64 pk2(float lo, float hi) {
    u64 r; asm("mov.b64 %0, {%1, %2};" : "=l"(r) : "f"(lo), "f"(hi)); return r;
}
static __device__ __forceinline__ void upk2(u64 v, float &lo, float &hi) {
    asm("mov.b64 {%0, %1}, %2;" : "=f"(lo), "=f"(hi) : "l"(v));
}
static __device__ __forceinline__ u64 fma2(u64 a, u64 b, u64 c) {
    u64 d; asm("fma.rn.f32x2 %0, %1, %2, %3;" : "=l"(d) : "l"(a), "l"(b), "l"(c)); return d;
}

// ---------------------------------------------------------------------------
// Kernel 1: data[i] = (g, dg/dx, dg/dy, dg/dz)  (central diff, edge-replicate)
// ---------------------------------------------------------------------------
__global__ void grad_kernel(const float* __restrict__ g) {
    int i = blockIdx.x * 256 + threadIdx.x;   // grid sized exactly NTOT/256
    int iz = i & 255, iy = (i >> 8) & 255, ix = i >> 16;
    float c  = __ldg(g + i);
    float xp = __ldg(g + (ix < 255 ? i + 65536 : i));
    float xm = __ldg(g + (ix > 0   ? i - 65536 : i));
    float yp = __ldg(g + (iy < 255 ? i + 256 : i));
    float ym = __ldg(g + (iy > 0   ? i - 256 : i));
    float zp = __ldg(g + (iz < 255 ? i + 1 : i));
    float zm = __ldg(g + (iz > 0   ? i - 1 : i));
    const float s = 63.75f;   // 1/(2*delta), delta = 2/255
    g_data[i] = make_float4(c, (xp - xm) * s, (yp - ym) * s, (zp - zm) * s);
}

// ---------------------------------------------------------------------------
// Fused main kernel helpers
// ---------------------------------------------------------------------------
static __device__ __forceinline__ float4 lerp4(float4 a, float4 b, float t) {
    float u = 1.0f - t;
    return make_float4(a.x * u + b.x * t, a.y * u + b.y * t,
                       a.z * u + b.z * t, a.w * u + b.w * t);
}

static __device__ __forceinline__ void load_w(const float* __restrict__ src,
                                              int nfloats, float* dst, int tid) {
    const float4* s = (const float4*)src;
    float4* d = (float4*)dst;
    int n4 = nfloats >> 2;
    for (int i = tid; i < n4; i += 256) d[i] = s[i];
}

static __device__ __forceinline__ void init_acc(const float* __restrict__ b,
                                                int tx, u64 acc[4][8]) {
#pragma unroll
    for (int j = 0; j < 8; j++) {
        int o = (j < 4) ? (4 * tx + j) : (64 + 4 * tx + (j - 4));
        float bv = __ldg(b + o);
        u64 p = pk2(bv, bv);
        acc[0][j] = p; acc[1][j] = p; acc[2][j] = p; acc[3][j] = p;
    }
}

static __device__ __forceinline__ void gemm_acc(const float* __restrict__ A, int K,
                                                const float* __restrict__ W,
                                                int tx, int ty, u64 acc[4][8]) {
    const float* Ap = A + 4 * ty;
    const float* Wp = W + 4 * tx;
#pragma unroll 4
    for (int k = 0; k < K; k++) {
        ulonglong2 A0 = *(const ulonglong2*)(Ap + k * 128);
        ulonglong2 A1 = *(const ulonglong2*)(Ap + k * 128 + 64);
        float4 wv0 = *(const float4*)(Wp + k * 128);
        float4 wv1 = *(const float4*)(Wp + k * 128 + 64);
        u64 a2[4]; a2[0] = A0.x; a2[1] = A0.y; a2[2] = A1.x; a2[3] = A1.y;
        u64 w2[8];
        w2[0] = pk2(wv0.x, wv0.x); w2[1] = pk2(wv0.y, wv0.y);
        w2[2] = pk2(wv0.z, wv0.z); w2[3] = pk2(wv0.w, wv0.w);
        w2[4] = pk2(wv1.x, wv1.x); w2[5] = pk2(wv1.y, wv1.y);
        w2[6] = pk2(wv1.z, wv1.z); w2[7] = pk2(wv1.w, wv1.w);
#pragma unroll
        for (int i = 0; i < 4; i++)
#pragma unroll
            for (int j = 0; j < 8; j++)
                acc[i][j] = fma2(a2[i], w2[j], acc[i][j]);
    }
}

static __device__ __forceinline__ void store_h(float* H, int tx, int ty,
                                               u64 acc[4][8], bool relu) {
#pragma unroll
    for (int j = 0; j < 8; j++) {
        int o = (j < 4) ? (4 * tx + j) : (64 + 4 * tx + (j - 4));
        float v[8];
#pragma unroll
        for (int i = 0; i < 4; i++) upk2(acc[i][j], v[2 * i], v[2 * i + 1]);
        if (relu) {
#pragma unroll
            for (int t = 0; t < 8; t++) v[t] = fmaxf(v[t], 0.0f);
        }
        *(float4*)(H + o * 128 + 4 * ty)      = make_float4(v[0], v[1], v[2], v[3]);
        *(float4*)(H + o * 128 + 64 + 4 * ty) = make_float4(v[4], v[5], v[6], v[7]);
    }
}

// ---------------------------------------------------------------------------
// Kernel 2: trilinear + pos-enc + MLP + Rodrigues, fused per 128-point tile
// ---------------------------------------------------------------------------
__global__ void __launch_bounds__(256, 1)
main_kernel(const float* __restrict__ x,
            const float* __restrict__ w0, const float* __restrict__ b0,
            const float* __restrict__ w1, const float* __restrict__ b1,
            const float* __restrict__ w2, const float* __restrict__ b2,
            const float* __restrict__ w3, const float* __restrict__ b3,
            const float* __restrict__ wo, const float* __restrict__ bo,
            float* __restrict__ out, int B) {
    extern __shared__ float smem[];
    float* F  = smem + F_OFF;
    float* H  = smem + H_OFF;
    float* Ws = smem + W_OFF;
    float4* RET = (float4*)(smem + RET_OFF);

    int tid = threadIdx.x;
    int tx = tid & 15, ty = tid >> 4;
    int pbase = blockIdx.x * 128;

    // ---------------- Phase 0: trilinear (tid<128) | pos-enc (tid>=128) ----
    {
        int p  = tid & 127;
        int gi = pbase + p;
        int gc = min(gi, B - 1);
        float px = __ldg(x + 3 * gc);
        float py = __ldg(x + 3 * gc + 1);
        float pz = __ldg(x + 3 * gc + 2);
        if (tid < 128) {
            float fx = (px + 1.0f) * 127.5f;
            float fy = (py + 1.0f) * 127.5f;
            float fz = (pz + 1.0f) * 127.5f;
            float flx = floorf(fx), fly = floorf(fy), flz = floorf(fz);
            float xd = fx - flx, yd = fy - fly, zd = fz - flz;
            int x0 = max(0, min(255, (int)flx));
            int x1 = max(0, min(255, (int)flx + 1));
            int y0 = max(0, min(255, (int)fly));
            int y1 = max(0, min(255, (int)fly + 1));
            int z0 = max(0, min(255, (int)flz));
            int z1 = max(0, min(255, (int)flz + 1));
            int bx0 = x0 << 16, bx1 = x1 << 16;
            int by0 = y0 << 8,  by1 = y1 << 8;
            float4 c000 = g_data[bx0 + by0 + z0];
            float4 c100 = g_data[bx1 + by0 + z0];
            float4 c010 = g_data[bx0 + by1 + z0];
            float4 c110 = g_data[bx1 + by1 + z0];
            float4 c001 = g_data[bx0 + by0 + z1];
            float4 c101 = g_data[bx1 + by0 + z1];
            float4 c011 = g_data[bx0 + by1 + z1];
            float4 c111 = g_data[bx1 + by1 + z1];
            float4 c00 = lerp4(c000, c100, xd);
            float4 c10 = lerp4(c010, c110, xd);
            float4 c01 = lerp4(c001, c101, xd);
            float4 c11 = lerp4(c011, c111, xd);
            float4 c0 = lerp4(c00, c10, yd);
            float4 c1 = lerp4(c01, c11, yd);
            RET[p] = lerp4(c0, c1, zd);
        } else {
            F[0 * 128 + p] = px;
            F[1 * 128 + p] = py;
            F[2 * 128 + p] = pz;
            float s0, c0, s1, c1, s2, c2;
            __sincosf(px, &s0, &c0);
            __sincosf(py, &s1, &c1);
            __sincosf(pz, &s2, &c2);
#pragma unroll
            for (int b = 0; b < 10; b++) {
                F[(3 + 6 * b + 0) * 128 + p] = s0;
                F[(3 + 6 * b + 1) * 128 + p] = s1;
                F[(3 + 6 * b + 2) * 128 + p] = s2;
                F[(3 + 6 * b + 3) * 128 + p] = c0;
                F[(3 + 6 * b + 4) * 128 + p] = c1;
                F[(3 + 6 * b + 5) * 128 + p] = c2;
                float ns0 = 2.0f * s0 * c0, nc0 = 1.0f - 2.0f * s0 * s0;
                float ns1 = 2.0f * s1 * c1, nc1 = 1.0f - 2.0f * s1 * s1;
                float ns2 = 2.0f * s2 * c2, nc2 = 1.0f - 2.0f * s2 * s2;
                s0 = ns0; c0 = nc0; s1 = ns1; c1 = nc1; s2 = ns2; c2 = nc2;
            }
        }
    }
    __syncthreads();

    u64 acc[4][8];

    // ---- Layer 0: feats(63) -> 128, relu ----
    load_w(w0, 63 * 128, Ws, tid);
    __syncthreads();
    init_acc(b0, tx, acc);
    gemm_acc(F, 63, Ws, tx, ty, acc);
    __syncthreads();
    store_h(H, tx, ty, acc, true);
    __syncthreads();

    // ---- Layer 1: 128 -> 128, relu ----
    load_w(w1, 128 * 128, Ws, tid);
    __syncthreads();
    init_acc(b1, tx, acc);
    gemm_acc(H, 128, Ws, tx, ty, acc);
    __syncthreads();
    store_h(H, tx, ty, acc, true);
    __syncthreads();

    // ---- Layer 2: 128 -> 128, relu ----
    load_w(w2, 128 * 128, Ws, tid);
    __syncthreads();
    init_acc(b2, tx, acc);
    gemm_acc(H, 128, Ws, tx, ty, acc);
    __syncthreads();
    store_h(H, tx, ty, acc, true);
    __syncthreads();

    // ---- Layer 3: concat(h2[128], feats[63]) = 191 -> 128, relu ----
    load_w(w3, 191 * 128, Ws, tid);
    __syncthreads();
    init_acc(b3, tx, acc);
    gemm_acc(H, 128, Ws, tx, ty, acc);
    gemm_acc(F, 63, Ws + 128 * 128, tx, ty, acc);
    __syncthreads();
    store_h(H, tx, ty, acc, true);
    __syncthreads();

    // ---- Head (128 -> 3) + Rodrigues epilogue, one thread per point ----
    if (tid < 128) {
        int p  = tid;
        int gi = pbase + p;
        float r0 = __ldg(bo), r1 = __ldg(bo + 1), r2 = __ldg(bo + 2);
#pragma unroll 8
        for (int o = 0; o < 128; o++) {
            float h = H[o * 128 + p];
            r0 = fmaf(h, __ldg(wo + 3 * o),     r0);
            r1 = fmaf(h, __ldg(wo + 3 * o + 1), r1);
            r2 = fmaf(h, __ldg(wo + 3 * o + 2), r2);
        }
        float theta = sqrtf(r0 * r0 + r1 * r1 + r2 * r2 + 1e-12f);
        float it = 1.0f / theta;
        float e0 = r0 * it, e1 = r1 * it, e2 = r2 * it;

        float4 ret = RET[p];
        float c0 = ret.y, c1 = ret.z, c2 = ret.w;
        float a = sqrtf(c0 * c0 + c1 * c1 + c2 * c2 + 1e-12f);
        float ia = 1.0f / a;
        float v0 = c0 * ia, v1 = c1 * ia, v2 = c2 * ia;

        float ct = cosf(theta), st = sinf(theta);
        float cr0 = e1 * v2 - e2 * v1;
        float cr1 = e2 * v0 - e0 * v2;
        float cr2 = e0 * v1 - e1 * v0;
        float dev = e0 * v0 + e1 * v1 + e2 * v2;
        float k1 = (1.0f - ct) * dev;
        float rot0 = a * (ct * v0 + st * cr0 + k1 * e0);
        float rot1 = a * (ct * v1 + st * cr1 + k1 * e1);
        float rot2 = a * (ct * v2 + st * cr2 + k1 * e2);

        if (gi < B) {
            out[gi] = ret.x;
            out[B + 3 * gi + 0] = c0;
            out[B + 3 * gi + 1] = c1;
            out[B + 3 * gi + 2] = c2;
            out[4 * B + 3 * gi + 0] = rot0;
            out[4 * B + 3 * gi + 1] = rot1;
            out[4 * B + 3 * gi + 2] = rot2;
        }
    }
}

// ---------------------------------------------------------------------------
// Launch
// ---------------------------------------------------------------------------
extern "C" void kernel_launch(void* const* d_in, const int* in_sizes, int n_in,
                              void* d_out, int out_size) {
    const float* x    = (const float*)d_in[0];
    const float* grid = (const float*)d_in[1];
    const float* w0   = (const float*)d_in[2];
    const float* b0   = (const float*)d_in[3];
    const float* w1   = (const float*)d_in[4];
    const float* b1   = (const float*)d_in[5];
    const float* w2   = (const float*)d_in[6];
    const float* b2   = (const float*)d_in[7];
    const float* w3   = (const float*)d_in[8];
    const float* b3   = (const float*)d_in[9];
    const float* wo   = (const float*)d_in[10];
    const float* bo   = (const float*)d_in[11];
    float* out = (float*)d_out;
    int B = in_sizes[0] / 3;

    cudaFuncSetAttribute(main_kernel,
                         cudaFuncAttributeMaxDynamicSharedMemorySize, SMEM_BYTES);

    grad_kernel<<<NTOT / 256, 256>>>(grid);
    main_kernel<<<(B + 127) / 128, 256, SMEM_BYTES>>>(
        x, w0, b0, w1, b1, w2, b2, w3, b3, wo, bo, out, B);
    (void)n_in; (void)out_size;
}

// round 7
// speedup vs baseline: 6.0769x; 6.0769x over previous
#include <cuda_runtime.h>
#include <cuda_bf16.h>

#define NTOT (256*256*256)

typedef unsigned int u32;

// ---------------- packed weight image (global + SMEM, same layout) ----------
#define PW_L0   0          // 4 kc  * 16 n * 32 lanes * 8B = 16384
#define PW_L1   16384      // 8 kc -> 32768
#define PW_L2   49152      // 8 kc -> 32768
#define PW_L3   81920      // 12 kc -> 49152
#define PB_OFF  131072     // 512 floats (b0,b1,b2,b3)
#define PWO_OFF 133120     // 384 floats
#define PBO_OFF 134656     // 3 floats
#define COPY_BYTES 134672
#define COPY_U4 (COPY_BYTES/16)

// SMEM extras
#define SM_FEAT 134672
#define FEAT_STRIDE 72                      // bf16 elems/row (144B, conflict-free frags)
#define SM_RET  (SM_FEAT + 256*FEAT_STRIDE*2)   // 171536
#define SMEM_BYTES (SM_RET + 256*16)            // 175632

__device__ float4 g_data[NTOT];                               // grid value + gradient
__device__ __align__(16) unsigned char g_wpack[COPY_BYTES];   // packed weights image

// pack two f32 -> bf16x2 (lo = first arg in low half)
#define CVTPACK(r, lo, hi) \
    asm("cvt.rn.satfinite.bf16x2.f32 %0, %1, %2;" : "=r"(r) : "f"(hi), "f"(lo))

static __device__ __forceinline__ void mma_bf16(float c[4], const u32 a[4], u32 b0, u32 b1) {
    asm("mma.sync.aligned.m16n8k16.row.col.f32.bf16.bf16.f32 "
        "{%0,%1,%2,%3}, {%4,%5,%6,%7}, {%8,%9}, {%0,%1,%2,%3};"
        : "+f"(c[0]), "+f"(c[1]), "+f"(c[2]), "+f"(c[3])
        : "r"(a[0]), "r"(a[1]), "r"(a[2]), "r"(a[3]), "r"(b0), "r"(b1));
}

// ---------------------------------------------------------------------------
// Kernel 1: grid value + central-difference gradient (exact fp32)
// ---------------------------------------------------------------------------
__global__ void grad_kernel(const float* __restrict__ g) {
    int i = blockIdx.x * 256 + threadIdx.x;
    int iz = i & 255, iy = (i >> 8) & 255, ix = i >> 16;
    float c  = __ldg(g + i);
    float xp = __ldg(g + (ix < 255 ? i + 65536 : i));
    float xm = __ldg(g + (ix > 0   ? i - 65536 : i));
    float yp = __ldg(g + (iy < 255 ? i + 256 : i));
    float ym = __ldg(g + (iy > 0   ? i - 256 : i));
    float zp = __ldg(g + (iz < 255 ? i + 1 : i));
    float zm = __ldg(g + (iz > 0   ? i - 1 : i));
    const float s = 63.75f;
    g_data[i] = make_float4(c, (xp - xm) * s, (yp - ym) * s, (zp - zm) * s);
}

// ---------------------------------------------------------------------------
// Kernel 2: pack weights into B-fragment order (bf16), biases/wo/bo as f32.
// Slot s within layer: lane = s&31, n = (s>>5)&15, kc = s>>9.
// b0 = {W[k0][o], W[k0+1][o]}, b1 = {W[k0+8][o], W[k0+9][o]},
// k0 = kc*16 + (lane&3)*2, o = n*8 + lane>>2, zero-padded past Kreal.
// ---------------------------------------------------------------------------
__global__ void prep_weights(const float* __restrict__ w0, const float* __restrict__ w1,
                             const float* __restrict__ w2, const float* __restrict__ w3,
                             const float* __restrict__ b0, const float* __restrict__ b1,
                             const float* __restrict__ b2, const float* __restrict__ b3,
                             const float* __restrict__ wo, const float* __restrict__ bo) {
    int t = blockIdx.x * 256 + threadIdx.x;
    if (t < 16384) {
        const float* w; int Kreal, base, s;
        if      (t < 2048)  { w = w0; Kreal = 63;  base = PW_L0; s = t; }
        else if (t < 6144)  { w = w1; Kreal = 128; base = PW_L1; s = t - 2048; }
        else if (t < 10240) { w = w2; Kreal = 128; base = PW_L2; s = t - 6144; }
        else                { w = w3; Kreal = 191; base = PW_L3; s = t - 10240; }
        int lane = s & 31, n = (s >> 5) & 15, kc = s >> 9;
        int k0 = kc * 16 + (lane & 3) * 2;
        int o  = n * 8 + (lane >> 2);
        float v00 = (k0     < Kreal) ? __ldg(w + (k0    ) * 128 + o) : 0.0f;
        float v01 = (k0 + 1 < Kreal) ? __ldg(w + (k0 + 1) * 128 + o) : 0.0f;
        float v10 = (k0 + 8 < Kreal) ? __ldg(w + (k0 + 8) * 128 + o) : 0.0f;
        float v11 = (k0 + 9 < Kreal) ? __ldg(w + (k0 + 9) * 128 + o) : 0.0f;
        u32 f0, f1;
        CVTPACK(f0, v00, v01);
        CVTPACK(f1, v10, v11);
        ((uint2*)(g_wpack + base))[s] = make_uint2(f0, f1);
    } else if (t < 16896) {
        int j = t - 16384;
        const float* bs = (j < 128) ? b0 : (j < 256) ? b1 : (j < 384) ? b2 : b3;
        *(float*)(g_wpack + PB_OFF + j * 4) = __ldg(bs + (j & 127));
    } else if (t < 17280) {
        int j = t - 16896;
        *(float*)(g_wpack + PWO_OFF + j * 4) = __ldg(wo + j);
    } else if (t < 17283) {
        int j = t - 17280;
        *(float*)(g_wpack + PBO_OFF + j * 4) = __ldg(bo + j);
    }
}

// ---------------------------------------------------------------------------
// bias+relu+pack epilogue: C frags -> next-layer A frags (register-only).
// Tile n maps to A[kc = n/2], slots (n&1)*2 + {0,1}.
// ---------------------------------------------------------------------------
static __device__ __forceinline__ void epi_convert(float acc[2][16][4],
                                                   const float* __restrict__ bs,
                                                   int l4, u32 A[2][8][4]) {
#pragma unroll
    for (int mt = 0; mt < 2; mt++)
#pragma unroll
        for (int n = 0; n < 16; n++) {
            float2 bb = *(const float2*)(bs + 8 * n + 2 * l4);
            float h0 = fmaxf(acc[mt][n][0] + bb.x, 0.0f);
            float h1 = fmaxf(acc[mt][n][1] + bb.y, 0.0f);
            float h2 = fmaxf(acc[mt][n][2] + bb.x, 0.0f);
            float h3 = fmaxf(acc[mt][n][3] + bb.y, 0.0f);
            u32 p01, p23;
            CVTPACK(p01, h0, h1);
            CVTPACK(p23, h2, h3);
            A[mt][n >> 1][(n & 1) * 2 + 0] = p01;
            A[mt][n >> 1][(n & 1) * 2 + 1] = p23;
        }
}

// ---------------------------------------------------------------------------
// Main fused kernel: 256 threads = 8 warps, 32 points/warp (2 m-tiles)
// ---------------------------------------------------------------------------
__global__ void __launch_bounds__(256, 1)
main_kernel(const float* __restrict__ x, float* __restrict__ out, int B) {
    extern __shared__ unsigned char smem[];
    int tid = threadIdx.x;
    int lane = tid & 31, wp = tid >> 5;
    int l4 = lane & 3, lr = lane >> 2;

    // ---- bulk weight image copy L2 -> SMEM ----
    {
        const uint4* s = (const uint4*)g_wpack;
        uint4* d = (uint4*)smem;
#pragma unroll 4
        for (int i = tid; i < COPY_U4; i += 256) d[i] = s[i];
    }

    int gi = blockIdx.x * 256 + tid;
    int gc = min(gi, B - 1);
    float px = __ldg(x + 3 * gc), py = __ldg(x + 3 * gc + 1), pz = __ldg(x + 3 * gc + 2);

    // ---- trilinear (exact fp32) -> RET smem ----
    {
        float fx = (px + 1.0f) * 127.5f, fy = (py + 1.0f) * 127.5f, fz = (pz + 1.0f) * 127.5f;
        float flx = floorf(fx), fly = floorf(fy), flz = floorf(fz);
        float xd = fx - flx, yd = fy - fly, zd = fz - flz;
        int x0 = max(0, min(255, (int)flx)), x1 = max(0, min(255, (int)flx + 1));
        int y0 = max(0, min(255, (int)fly)), y1 = max(0, min(255, (int)fly + 1));
        int z0 = max(0, min(255, (int)flz)), z1 = max(0, min(255, (int)flz + 1));
        int bx0 = x0 << 16, bx1 = x1 << 16, by0 = y0 << 8, by1 = y1 << 8;
        float4 c000 = g_data[bx0 + by0 + z0], c100 = g_data[bx1 + by0 + z0];
        float4 c010 = g_data[bx0 + by1 + z0], c110 = g_data[bx1 + by1 + z0];
        float4 c001 = g_data[bx0 + by0 + z1], c101 = g_data[bx1 + by0 + z1];
        float4 c011 = g_data[bx0 + by1 + z1], c111 = g_data[bx1 + by1 + z1];
        float xu = 1.0f - xd, yu = 1.0f - yd, zu = 1.0f - zd;
        float a0x = c000.x * xu + c100.x * xd, a0y = c000.y * xu + c100.y * xd,
              a0z = c000.z * xu + c100.z * xd, a0w = c000.w * xu + c100.w * xd;
        float b0x = c010.x * xu + c110.x * xd, b0y = c010.y * xu + c110.y * xd,
              b0z = c010.z * xu + c110.z * xd, b0w = c010.w * xu + c110.w * xd;
        float a1x = c001.x * xu + c101.x * xd, a1y = c001.y * xu + c101.y * xd,
              a1z = c001.z * xu + c101.z * xd, a1w = c001.w * xu + c101.w * xd;
        float b1x = c011.x * xu + c111.x * xd, b1y = c011.y * xu + c111.y * xd,
              b1z = c011.z * xu + c111.z * xd, b1w = c011.w * xu + c111.w * xd;
        float e0x = a0x * yu + b0x * yd, e0y = a0y * yu + b0y * yd,
              e0z = a0z * yu + b0z * yd, e0w = a0w * yu + b0w * yd;
        float e1x = a1x * yu + b1x * yd, e1y = a1y * yu + b1y * yd,
              e1z = a1z * yu + b1z * yd, e1w = a1w * yu + b1w * yd;
        ((float4*)(smem + SM_RET))[tid] =
            make_float4(e0x * zu + e1x * zd, e0y * zu + e1y * zd,
                        e0z * zu + e1z * zd, e0w * zu + e1w * zd);
    }

    // ---- feats (63 + zero pad) -> SMEM row (bf16, padded stride) ----
    {
        float f[64];
        f[0] = px; f[1] = py; f[2] = pz; f[63] = 0.0f;
        float s0, c0, s1, c1, s2, c2;
        __sincosf(px, &s0, &c0); __sincosf(py, &s1, &c1); __sincosf(pz, &s2, &c2);
#pragma unroll
        for (int b = 0; b < 10; b++) {
            f[3 + 6 * b + 0] = s0; f[3 + 6 * b + 1] = s1; f[3 + 6 * b + 2] = s2;
            f[3 + 6 * b + 3] = c0; f[3 + 6 * b + 4] = c1; f[3 + 6 * b + 5] = c2;
            float ns0 = 2.0f * s0 * c0, nc0 = 1.0f - 2.0f * s0 * s0;
            float ns1 = 2.0f * s1 * c1, nc1 = 1.0f - 2.0f * s1 * s1;
            float ns2 = 2.0f * s2 * c2, nc2 = 1.0f - 2.0f * s2 * s2;
            s0 = ns0; c0 = nc0; s1 = ns1; c1 = nc1; s2 = ns2; c2 = nc2;
        }
        u32* frow = (u32*)((__nv_bfloat16*)(smem + SM_FEAT) + tid * FEAT_STRIDE);
#pragma unroll
        for (int j = 0; j < 32; j++) {
            u32 p; CVTPACK(p, f[2 * j], f[2 * j + 1]);
            frow[j] = p;
        }
    }
    __syncthreads();   // weights + feats + RET visible; no more CTA syncs needed

    const __nv_bfloat16* FS = (const __nv_bfloat16*)(smem + SM_FEAT);
    const float* bias = (const float*)(smem + PB_OFF);
    int rbase0 = 32 * wp + lr;      // m-tile 0 row
    float acc[2][16][4];
    u32 A[2][8][4];

    // ================= layer 0: feats (4 kc) -> 128 =================
    {
        u32 AF[2][4][4];
#pragma unroll
        for (int mt = 0; mt < 2; mt++) {
            const __nv_bfloat16* rp = FS + (rbase0 + 16 * mt) * FEAT_STRIDE + 2 * l4;
#pragma unroll
            for (int kc = 0; kc < 4; kc++) {
                AF[mt][kc][0] = *(const u32*)(rp + kc * 16);
                AF[mt][kc][1] = *(const u32*)(rp + kc * 16 + 8 * FEAT_STRIDE);
                AF[mt][kc][2] = *(const u32*)(rp + kc * 16 + 8);
                AF[mt][kc][3] = *(const u32*)(rp + kc * 16 + 8 * FEAT_STRIDE + 8);
            }
        }
        const uint2* W = (const uint2*)(smem + PW_L0);
#pragma unroll
        for (int mt = 0; mt < 2; mt++)
#pragma unroll
            for (int n = 0; n < 16; n++)
#pragma unroll
                for (int i = 0; i < 4; i++) acc[mt][n][i] = 0.0f;
#pragma unroll
        for (int kc = 0; kc < 4; kc++)
#pragma unroll
            for (int n = 0; n < 16; n++) {
                uint2 b = W[(kc * 16 + n) * 32 + lane];
                mma_bf16(acc[0][n], AF[0][kc], b.x, b.y);
                mma_bf16(acc[1][n], AF[1][kc], b.x, b.y);
            }
        epi_convert(acc, bias, l4, A);
    }

    // ================= layers 1 & 2: 128 -> 128 =================
#pragma unroll
    for (int L = 0; L < 2; L++) {
        const uint2* W = (const uint2*)(smem + (L == 0 ? PW_L1 : PW_L2));
#pragma unroll
        for (int mt = 0; mt < 2; mt++)
#pragma unroll
            for (int n = 0; n < 16; n++)
#pragma unroll
                for (int i = 0; i < 4; i++) acc[mt][n][i] = 0.0f;
#pragma unroll
        for (int kc = 0; kc < 8; kc++)
#pragma unroll
            for (int n = 0; n < 16; n++) {
                uint2 b = W[(kc * 16 + n) * 32 + lane];
                mma_bf16(acc[0][n], A[0][kc], b.x, b.y);
                mma_bf16(acc[1][n], A[1][kc], b.x, b.y);
            }
        epi_convert(acc, bias + 128 * (L + 1), l4, A);
    }

    // ================= layer 3: concat(h[128], feats[63+pad]) = 192 k =====
    {
        const uint2* W = (const uint2*)(smem + PW_L3);
#pragma unroll
        for (int mt = 0; mt < 2; mt++)
#pragma unroll
            for (int n = 0; n < 16; n++)
#pragma unroll
                for (int i = 0; i < 4; i++) acc[mt][n][i] = 0.0f;
#pragma unroll
        for (int kc = 0; kc < 8; kc++)
#pragma unroll
            for (int n = 0; n < 16; n++) {
                uint2 b = W[(kc * 16 + n) * 32 + lane];
                mma_bf16(acc[0][n], A[0][kc], b.x, b.y);
                mma_bf16(acc[1][n], A[1][kc], b.x, b.y);
            }
#pragma unroll
        for (int kc = 8; kc < 12; kc++) {
            u32 AF[2][4];
#pragma unroll
            for (int mt = 0; mt < 2; mt++) {
                const __nv_bfloat16* rp = FS + (rbase0 + 16 * mt) * FEAT_STRIDE
                                          + (kc - 8) * 16 + 2 * l4;
                AF[mt][0] = *(const u32*)rp;
                AF[mt][1] = *(const u32*)(rp + 8 * FEAT_STRIDE);
                AF[mt][2] = *(const u32*)(rp + 8);
                AF[mt][3] = *(const u32*)(rp + 8 * FEAT_STRIDE + 8);
            }
#pragma unroll
            for (int n = 0; n < 16; n++) {
                uint2 b = W[(kc * 16 + n) * 32 + lane];
                mma_bf16(acc[0][n], AF[0], b.x, b.y);
                mma_bf16(acc[1][n], AF[1], b.x, b.y);
            }
        }
        // bias + relu in place (floats kept for head)
        const float* b3s = bias + 384;
#pragma unroll
        for (int mt = 0; mt < 2; mt++)
#pragma unroll
            for (int n = 0; n < 16; n++) {
                float2 bb = *(const float2*)(b3s + 8 * n + 2 * l4);
                acc[mt][n][0] = fmaxf(acc[mt][n][0] + bb.x, 0.0f);
                acc[mt][n][1] = fmaxf(acc[mt][n][1] + bb.y, 0.0f);
                acc[mt][n][2] = fmaxf(acc[mt][n][2] + bb.x, 0.0f);
                acc[mt][n][3] = fmaxf(acc[mt][n][3] + bb.y, 0.0f);
            }
    }

    // ================= head: h @ wo + bo, quad-reduce, Rodrigues ==========
    {
        const float* wos = (const float*)(smem + PWO_OFF);
        float pd[2][2][3];
#pragma unroll
        for (int mt = 0; mt < 2; mt++)
#pragma unroll
            for (int hf = 0; hf < 2; hf++)
#pragma unroll
                for (int j = 0; j < 3; j++) pd[mt][hf][j] = 0.0f;
#pragma unroll
        for (int n = 0; n < 16; n++) {
            int o = 8 * n + 2 * l4;
            float w00 = wos[3 * o],     w01 = wos[3 * o + 1], w02 = wos[3 * o + 2];
            float w10 = wos[3 * o + 3], w11 = wos[3 * o + 4], w12 = wos[3 * o + 5];
#pragma unroll
            for (int mt = 0; mt < 2; mt++) {
                pd[mt][0][0] += acc[mt][n][0] * w00 + acc[mt][n][1] * w10;
                pd[mt][0][1] += acc[mt][n][0] * w01 + acc[mt][n][1] * w11;
                pd[mt][0][2] += acc[mt][n][0] * w02 + acc[mt][n][1] * w12;
                pd[mt][1][0] += acc[mt][n][2] * w00 + acc[mt][n][3] * w10;
                pd[mt][1][1] += acc[mt][n][2] * w01 + acc[mt][n][3] * w11;
                pd[mt][1][2] += acc[mt][n][2] * w02 + acc[mt][n][3] * w12;
            }
        }
#pragma unroll
        for (int mt = 0; mt < 2; mt++)
#pragma unroll
            for (int hf = 0; hf < 2; hf++)
#pragma unroll
                for (int j = 0; j < 3; j++) {
                    float v = pd[mt][hf][j];
                    v += __shfl_xor_sync(0xFFFFFFFF, v, 1);
                    v += __shfl_xor_sync(0xFFFFFFFF, v, 2);
                    pd[mt][hf][j] = v;
                }
        if (l4 == 0) {
            const float* bos = (const float*)(smem + PBO_OFF);
#pragma unroll
            for (int mt = 0; mt < 2; mt++)
#pragma unroll
                for (int hf = 0; hf < 2; hf++) {
                    int lp = 32 * wp + 16 * mt + lr + 8 * hf;
                    int g  = blockIdx.x * 256 + lp;
                    float r0 = pd[mt][hf][0] + bos[0];
                    float r1 = pd[mt][hf][1] + bos[1];
                    float r2 = pd[mt][hf][2] + bos[2];
                    float theta = sqrtf(r0 * r0 + r1 * r1 + r2 * r2 + 1e-12f);
                    float it = 1.0f / theta;
                    float e0 = r0 * it, e1 = r1 * it, e2 = r2 * it;
                    float4 ret = ((const float4*)(smem + SM_RET))[lp];
                    float cc0 = ret.y, cc1 = ret.z, cc2 = ret.w;
                    float a = sqrtf(cc0 * cc0 + cc1 * cc1 + cc2 * cc2 + 1e-12f);
                    float ia = 1.0f / a;
                    float v0 = cc0 * ia, v1 = cc1 * ia, v2 = cc2 * ia;
                    float ct = cosf(theta), st = sinf(theta);
                    float cr0 = e1 * v2 - e2 * v1;
                    float cr1 = e2 * v0 - e0 * v2;
                    float cr2 = e0 * v1 - e1 * v0;
                    float k1 = (1.0f - ct) * (e0 * v0 + e1 * v1 + e2 * v2);
                    if (g < B) {
                        out[g] = ret.x;
                        out[B + 3 * g + 0] = cc0;
                        out[B + 3 * g + 1] = cc1;
                        out[B + 3 * g + 2] = cc2;
                        out[4 * B + 3 * g + 0] = a * (ct * v0 + st * cr0 + k1 * e0);
                        out[4 * B + 3 * g + 1] = a * (ct * v1 + st * cr1 + k1 * e1);
                        out[4 * B + 3 * g + 2] = a * (ct * v2 + st * cr2 + k1 * e2);
                    }
                }
        }
    }
}

// ---------------------------------------------------------------------------
extern "C" void kernel_launch(void* const* d_in, const int* in_sizes, int n_in,
                              void* d_out, int out_size) {
    const float* x    = (const float*)d_in[0];
    const float* grid = (const float*)d_in[1];
    const float* w0   = (const float*)d_in[2];
    const float* b0   = (const float*)d_in[3];
    const float* w1   = (const float*)d_in[4];
    const float* b1   = (const float*)d_in[5];
    const float* w2   = (const float*)d_in[6];
    const float* b2   = (const float*)d_in[7];
    const float* w3   = (const float*)d_in[8];
    const float* b3   = (const float*)d_in[9];
    const float* wo   = (const float*)d_in[10];
    const float* bo   = (const float*)d_in[11];
    float* out = (float*)d_out;
    int B = in_sizes[0] / 3;

    cudaFuncSetAttribute(main_kernel,
                         cudaFuncAttributeMaxDynamicSharedMemorySize, SMEM_BYTES);

    grad_kernel<<<NTOT / 256, 256>>>(grid);
    prep_weights<<<68, 256>>>(w0, w1, w2, w3, b0, b1, b2, b3, wo, bo);
    main_kernel<<<(B + 255) / 256, 256, SMEM_BYTES>>>(x, out, B);
    (void)n_in; (void)out_size;
}